// round 1
// baseline (speedup 1.0000x reference)
#include <cuda_runtime.h>
#include <cstdint>

#define N_NODES 50000
#define EMB     128
#define R_REL   9
#define S_REL   18            // 2*R
#define NW      19            // 2*R+1
#define N_EDGES 800000
#define E2      (2*N_EDGES)
#define YSTRIDE (NW*EMB)      // 2432
#define W_LAYER (NW*EMB*EMB)  // 311296
#define B_LAYER (NW*EMB)      // 2432

// -------- scratch (device globals; no runtime allocation allowed) --------
__device__ int   g_count[S_REL * N_NODES];   // raw count per (s, node)
__device__ float g_alpha[S_REL * N_NODES];   // suffix products
__device__ float g_gamma[S_REL * N_NODES];   // alpha * raw count
__device__ float g_A[N_NODES];               // full product
__device__ int   g_deg[N_NODES];
__device__ int   g_off[N_NODES + 1];
__device__ int   g_cur[N_NODES];
__device__ int   g_rec[E2];                  // packed (s<<16)|src, sorted by dest
__device__ float g_Y[(size_t)N_NODES * YSTRIDE];   // ~487 MB
__device__ float g_H[(size_t)N_NODES * EMB];       // inter-layer hidden

// ---------------------------- preprocessing ----------------------------
__global__ void zero_kernel() {
    int total = S_REL * N_NODES + N_NODES;
    for (int idx = blockIdx.x * blockDim.x + threadIdx.x; idx < total;
         idx += gridDim.x * blockDim.x) {
        if (idx < S_REL * N_NODES) g_count[idx] = 0;
        else                       g_deg[idx - S_REL * N_NODES] = 0;
    }
}

__global__ void hist_kernel(const int* __restrict__ ei, const int* __restrict__ et) {
    int idx = blockIdx.x * blockDim.x + threadIdx.x;
    if (idx >= E2) return;
    int dest, s;
    if (idx < N_EDGES) {                 // forward: dest = ei[0], slot = r
        dest = ei[idx];
        s    = et[idx];
    } else {                             // inverse: dest = ei[1], slot = r + R
        int e = idx - N_EDGES;
        dest = ei[N_EDGES + e];
        s    = et[e] + R_REL;
    }
    atomicAdd(&g_count[s * N_NODES + dest], 1);
    atomicAdd(&g_deg[dest], 1);
}

// per-node suffix products over the reference's step order:
// step k: r = k/2, inv = k&1, s = r + 9*inv
__global__ void alpha_kernel() {
    int i = blockIdx.x * blockDim.x + threadIdx.x;
    if (i >= N_NODES) return;
    int cnt[S_REL];
#pragma unroll
    for (int s = 0; s < S_REL; s++) cnt[s] = g_count[s * N_NODES + i];
    float suffix = 1.0f;
#pragma unroll
    for (int k = S_REL - 1; k >= 0; k--) {
        int s = (k >> 1) + R_REL * (k & 1);
        int c = cnt[s];
        float f = 2.0f / (float)(c > 0 ? c : 1);
        suffix *= f;
        g_alpha[s * N_NODES + i] = suffix;
        g_gamma[s * N_NODES + i] = suffix * (float)c;   // raw count for bias term
    }
    g_A[i] = suffix;
}

__global__ void scan_kernel() {
    __shared__ int sh[1024];
    int tid = threadIdx.x;
    int carry = 0;
    if (tid == 0) g_off[0] = 0;
    for (int base = 0; base < N_NODES; base += 1024) {
        int i = base + tid;
        int v = (i < N_NODES) ? g_deg[i] : 0;
        sh[tid] = v;
        __syncthreads();
        for (int off = 1; off < 1024; off <<= 1) {
            int t = (tid >= off) ? sh[tid - off] : 0;
            __syncthreads();
            sh[tid] += t;
            __syncthreads();
        }
        int inc = sh[tid];
        if (i < N_NODES) {
            g_off[i + 1] = carry + inc;       // inclusive
            g_cur[i]     = carry + inc - v;   // exclusive (cursor copy)
        }
        int tot = sh[1023];
        __syncthreads();
        carry += tot;
    }
}

__global__ void scatter_kernel(const int* __restrict__ ei, const int* __restrict__ et) {
    int idx = blockIdx.x * blockDim.x + threadIdx.x;
    if (idx >= E2) return;
    int dest, src, s;
    if (idx < N_EDGES) {
        dest = ei[idx];
        src  = ei[N_EDGES + idx];
        s    = et[idx];
    } else {
        int e = idx - N_EDGES;
        dest = ei[N_EDGES + e];
        src  = ei[e];
        s    = et[e] + R_REL;
    }
    int pos = atomicAdd(&g_cur[dest], 1);
    g_rec[pos] = src | (s << 16);
}

// ------------------------------- GEMM ----------------------------------
// Y[m, s*128 + j] = sum_k X[m,k] * W[s,k,j]
// block: 128(M) x 128(N = one relation slot), K chunked by 32. 256 threads.
__global__ void __launch_bounds__(256) gemm_kernel(const float* __restrict__ X,
                                                   const float* __restrict__ Wl) {
    __shared__ float As[32][132];   // [k][m], pad 132 keeps 16B align + 4-way max STS conflict
    __shared__ float Bs[32][128];   // [k][j]
    int s  = blockIdx.y;
    int m0 = blockIdx.x * 128;
    const float* Wb = Wl + s * (EMB * EMB);
    int tid = threadIdx.x;
    int tx = tid & 15, ty = tid >> 4;
    float acc[8][8] = {};

    for (int k0 = 0; k0 < 128; k0 += 32) {
        // A chunk: 128 rows x 32 cols -> 1024 float4, 4 per thread, transposed into As
#pragma unroll
        for (int u = 0; u < 4; u++) {
            int idx = tid + u * 256;
            int row = idx >> 3;      // 0..127 (m)
            int c4  = idx & 7;       // 0..7  (k/4)
            int gm  = m0 + row;
            float4 v = (gm < N_NODES)
                ? *(const float4*)(X + (size_t)gm * EMB + k0 + c4 * 4)
                : make_float4(0.f, 0.f, 0.f, 0.f);
            As[c4 * 4 + 0][row] = v.x;
            As[c4 * 4 + 1][row] = v.y;
            As[c4 * 4 + 2][row] = v.z;
            As[c4 * 4 + 3][row] = v.w;
        }
        // B chunk: 32 rows x 128 cols
#pragma unroll
        for (int u = 0; u < 4; u++) {
            int idx = tid + u * 256;
            int row = idx >> 5;      // 0..31
            int c4  = idx & 31;
            *(float4*)&Bs[row][c4 * 4] =
                *(const float4*)(Wb + (size_t)(k0 + row) * EMB + c4 * 4);
        }
        __syncthreads();
#pragma unroll 8
        for (int k = 0; k < 32; k++) {
            float a[8], b[8];
            *(float4*)&a[0] = *(const float4*)&As[k][ty * 8];
            *(float4*)&a[4] = *(const float4*)&As[k][ty * 8 + 4];
            *(float4*)&b[0] = *(const float4*)&Bs[k][tx * 8];
            *(float4*)&b[4] = *(const float4*)&Bs[k][tx * 8 + 4];
#pragma unroll
            for (int i2 = 0; i2 < 8; i2++)
#pragma unroll
                for (int j2 = 0; j2 < 8; j2++)
                    acc[i2][j2] = fmaf(a[i2], b[j2], acc[i2][j2]);
        }
        __syncthreads();
    }
#pragma unroll
    for (int i2 = 0; i2 < 8; i2++) {
        int gm = m0 + ty * 8 + i2;
        if (gm < N_NODES) {
            float* dst = g_Y + (size_t)gm * YSTRIDE + s * EMB + tx * 8;
            *(float4*)dst       = *(float4*)&acc[i2][0];
            *(float4*)(dst + 4) = *(float4*)&acc[i2][4];
        }
    }
}

// --------------------------- node epilogue -----------------------------
// one warp per node: init = A*(Y_self + b18) + sum_s gamma_s*b_s, then
// accumulate alpha_s[dest] * Y[src, s-block] over sorted incident edges.
__global__ void __launch_bounds__(256) node_kernel(const float* __restrict__ bl,
                                                   float* __restrict__ Xout,
                                                   int do_relu) {
    int warp = (blockIdx.x << 3) + (threadIdx.x >> 5);
    if (warp >= N_NODES) return;
    int i  = warp;
    int fo = (threadIdx.x & 31) << 2;   // feature offset (4 floats per lane)

    float Ai = g_A[i];
    float4 acc;
    {
        float4 ys  = *(const float4*)(g_Y + (size_t)i * YSTRIDE + 2 * R_REL * EMB + fo);
        float4 b18 = *(const float4*)(bl + 2 * R_REL * EMB + fo);
        acc.x = Ai * (ys.x + b18.x);
        acc.y = Ai * (ys.y + b18.y);
        acc.z = Ai * (ys.z + b18.z);
        acc.w = Ai * (ys.w + b18.w);
    }
#pragma unroll
    for (int s = 0; s < S_REL; s++) {
        float g = g_gamma[s * N_NODES + i];
        float4 bs = *(const float4*)(bl + s * EMB + fo);
        acc.x = fmaf(g, bs.x, acc.x);
        acc.y = fmaf(g, bs.y, acc.y);
        acc.z = fmaf(g, bs.z, acc.z);
        acc.w = fmaf(g, bs.w, acc.w);
    }
    int e0 = g_off[i], e1 = g_off[i + 1];
    for (int e = e0; e < e1; e++) {
        int rec = g_rec[e];
        int src = rec & 0xFFFF;
        int s   = rec >> 16;
        float al = g_alpha[s * N_NODES + i];
        float4 y = *(const float4*)(g_Y + (size_t)src * YSTRIDE + (s << 7) + fo);
        acc.x = fmaf(al, y.x, acc.x);
        acc.y = fmaf(al, y.y, acc.y);
        acc.z = fmaf(al, y.z, acc.z);
        acc.w = fmaf(al, y.w, acc.w);
    }
    if (do_relu) {
        acc.x = fmaxf(acc.x, 0.f);
        acc.y = fmaxf(acc.y, 0.f);
        acc.z = fmaxf(acc.z, 0.f);
        acc.w = fmaxf(acc.w, 0.f);
    }
    *(float4*)(Xout + (size_t)i * EMB + fo) = acc;
}

// ------------------------------ launch ---------------------------------
extern "C" void kernel_launch(void* const* d_in, const int* in_sizes, int n_in,
                              void* d_out, int out_size) {
    const int*   ei  = (const int*)d_in[0];     // [2, E]
    const int*   et  = (const int*)d_in[1];     // [E]
    const float* emb = (const float*)d_in[2];   // [N, 128]
    const float* w   = (const float*)d_in[3];   // [2, 19, 128, 128]
    const float* b   = (const float*)d_in[4];   // [2, 19, 128]
    float* out = (float*)d_out;

    float* hptr = nullptr;
    cudaGetSymbolAddress((void**)&hptr, g_H);

    zero_kernel<<<1024, 256>>>();
    hist_kernel<<<(E2 + 255) / 256, 256>>>(ei, et);
    alpha_kernel<<<(N_NODES + 255) / 256, 256>>>();
    scan_kernel<<<1, 1024>>>();
    scatter_kernel<<<(E2 + 255) / 256, 256>>>(ei, et);

    dim3 ggrid((N_NODES + 127) / 128, NW);
    int ngrid = (N_NODES + 7) / 8;

    // layer 0: X = embeddings -> H (relu)
    gemm_kernel<<<ggrid, 256>>>(emb, w);
    node_kernel<<<ngrid, 256>>>(b, hptr, 1);
    // layer 1: X = H -> out (no relu)
    gemm_kernel<<<ggrid, 256>>>(hptr, w + W_LAYER);
    node_kernel<<<ngrid, 256>>>(b + B_LAYER, out, 0);
}

// round 3
// speedup vs baseline: 1.9564x; 1.9564x over previous
#include <cuda_runtime.h>
#include <cuda_bf16.h>
#include <cstdint>

#define N_NODES 50000
#define EMB     128
#define R_REL   9
#define S_REL   18            // 2*R
#define NW      19            // 2*R+1
#define N_EDGES 800000
#define E2      (2*N_EDGES)
#define YSTRIDE (NW*EMB)      // 2432
#define W_LAYER (NW*EMB*EMB)  // 311296
#define B_LAYER (NW*EMB)      // 2432
#define TILES_M 391           // ceil(50000/128)
#define TILES_TOT (NW*TILES_M)

// smem layout (bytes); bf16 row stride 136 elems = 272B (conflict-free for ldmatrix)
#define SROW    272
#define ATILE   34816          // 128 * 272
#define OFF_AHI 0              // Ahi[2]
#define OFF_ALO 69632          // Alo[2]
#define OFF_BHI 139264
#define OFF_BLO 174080
#define GEMM_DSM 208896

// -------- scratch (device globals; no runtime allocation allowed) --------
__device__ int   g_count[S_REL * N_NODES];
__device__ float g_alpha[S_REL * N_NODES];
__device__ float g_gamma[S_REL * N_NODES];
__device__ float g_A[N_NODES];
__device__ int   g_deg[N_NODES];
__device__ int   g_off[N_NODES + 1];
__device__ int   g_cur[N_NODES];
__device__ int   g_bsum[64];
__device__ int   g_boff[64];
__device__ int   g_rec[E2];                        // packed (s<<16)|src, sorted by dest
__device__ float g_Y[(size_t)N_NODES * YSTRIDE];   // ~487 MB
__device__ float g_H[(size_t)N_NODES * EMB];
__device__ __nv_bfloat16 g_Xhi[(size_t)N_NODES * EMB];
__device__ __nv_bfloat16 g_Xlo[(size_t)N_NODES * EMB];
__device__ __nv_bfloat16 g_Wthi[2 * NW * EMB * EMB];   // transposed: [l][s][j][k]
__device__ __nv_bfloat16 g_Wtlo[2 * NW * EMB * EMB];

// ------------------------- PTX helpers (base sm_100) -------------------------
__device__ __forceinline__ uint32_t smem_u32(const void* p) {
    uint32_t a;
    asm("{ .reg .u64 t; cvta.to.shared.u64 t, %1; cvt.u32.u64 %0, t; }" : "=r"(a) : "l"(p));
    return a;
}
__device__ __forceinline__ void cp_async16(uint32_t dst, const void* src, int srcsize) {
    asm volatile("cp.async.cg.shared.global [%0], [%1], 16, %2;"
                 :: "r"(dst), "l"(src), "r"(srcsize) : "memory");
}
#define CP_COMMIT() asm volatile("cp.async.commit_group;" ::: "memory")
#define CP_WAIT0()  asm volatile("cp.async.wait_group 0;" ::: "memory")

__device__ __forceinline__ void ldsm_x4(uint32_t* r, uint32_t addr) {
    asm volatile("ldmatrix.sync.aligned.m8n8.x4.shared.b16 {%0,%1,%2,%3}, [%4];"
                 : "=r"(r[0]), "=r"(r[1]), "=r"(r[2]), "=r"(r[3]) : "r"(addr));
}
__device__ __forceinline__ void mma_bf16(float* c, const uint32_t* a, const uint32_t* b) {
    asm volatile("mma.sync.aligned.m16n8k16.row.col.f32.bf16.bf16.f32 "
                 "{%0,%1,%2,%3}, {%4,%5,%6,%7}, {%8,%9}, {%0,%1,%2,%3};"
                 : "+f"(c[0]), "+f"(c[1]), "+f"(c[2]), "+f"(c[3])
                 : "r"(a[0]), "r"(a[1]), "r"(a[2]), "r"(a[3]), "r"(b[0]), "r"(b[1]));
}

// ---------------------------- preprocessing ----------------------------
__global__ void zero_kernel() {
    int total = S_REL * N_NODES + N_NODES;
    for (int idx = blockIdx.x * blockDim.x + threadIdx.x; idx < total;
         idx += gridDim.x * blockDim.x) {
        if (idx < S_REL * N_NODES) g_count[idx] = 0;
        else                       g_deg[idx - S_REL * N_NODES] = 0;
    }
}

__global__ void hist_kernel(const int* __restrict__ ei, const int* __restrict__ et) {
    int idx = blockIdx.x * blockDim.x + threadIdx.x;
    if (idx >= E2) return;
    int dest, s;
    if (idx < N_EDGES) { dest = ei[idx]; s = et[idx]; }
    else { int e = idx - N_EDGES; dest = ei[N_EDGES + e]; s = et[e] + R_REL; }
    atomicAdd(&g_count[s * N_NODES + dest], 1);
    atomicAdd(&g_deg[dest], 1);
}

__global__ void alpha_kernel() {
    int i = blockIdx.x * blockDim.x + threadIdx.x;
    if (i >= N_NODES) return;
    int cnt[S_REL];
#pragma unroll
    for (int s = 0; s < S_REL; s++) cnt[s] = g_count[s * N_NODES + i];
    float suffix = 1.0f;
#pragma unroll
    for (int k = S_REL - 1; k >= 0; k--) {
        int s = (k >> 1) + R_REL * (k & 1);
        int c = cnt[s];
        float f = 2.0f / (float)(c > 0 ? c : 1);
        suffix *= f;
        g_alpha[s * N_NODES + i] = suffix;
        g_gamma[s * N_NODES + i] = suffix * (float)c;
    }
    g_A[i] = suffix;
}

__global__ void scan1_kernel() {
    __shared__ int wsum[32];
    int b = blockIdx.x, t = threadIdx.x;
    int i = b * 1024 + t;
    int lane = t & 31, w = t >> 5;
    int v = (i < N_NODES) ? g_deg[i] : 0;
    int val = v;
#pragma unroll
    for (int d = 1; d < 32; d <<= 1) {
        int u = __shfl_up_sync(0xFFFFFFFF, val, d);
        if (lane >= d) val += u;
    }
    if (lane == 31) wsum[w] = val;
    __syncthreads();
    if (w == 0) {
        int x = wsum[lane];
#pragma unroll
        for (int d = 1; d < 32; d <<= 1) {
            int u = __shfl_up_sync(0xFFFFFFFF, x, d);
            if (lane >= d) x += u;
        }
        wsum[lane] = x;
    }
    __syncthreads();
    int incl = val + (w > 0 ? wsum[w - 1] : 0);
    if (i < N_NODES) g_off[i + 1] = incl;
    if (t == 0) g_bsum[b] = wsum[31];
}
__global__ void scan2_kernel(int nb) {
    if (threadIdx.x == 0) {
        int run = 0;
        for (int b = 0; b < nb; b++) { g_boff[b] = run; run += g_bsum[b]; }
    }
}
__global__ void scan3_kernel() {
    int i = blockIdx.x * blockDim.x + threadIdx.x;
    if (i == 0) g_off[0] = 0;
    if (i >= N_NODES) return;
    int off = g_off[i + 1] + g_boff[i >> 10];
    g_off[i + 1] = off;
    g_cur[i] = off - g_deg[i];
}

__global__ void scatter_kernel(const int* __restrict__ ei, const int* __restrict__ et) {
    int idx = blockIdx.x * blockDim.x + threadIdx.x;
    if (idx >= E2) return;
    int dest, src, s;
    if (idx < N_EDGES) { dest = ei[idx]; src = ei[N_EDGES + idx]; s = et[idx]; }
    else { int e = idx - N_EDGES; dest = ei[N_EDGES + e]; src = ei[e]; s = et[e] + R_REL; }
    int pos = atomicAdd(&g_cur[dest], 1);
    g_rec[pos] = src | (s << 16);
}

// ------------------------ bf16 split conversions ------------------------
__global__ void convw_kernel(const float* __restrict__ w) {
    int idx = blockIdx.x * blockDim.x + threadIdx.x;
    int total = 2 * NW * EMB * EMB;
    if (idx >= total) return;
    int j = idx & 127;
    int k = (idx >> 7) & 127;
    int ls = idx >> 14;
    float v = w[idx];
    __nv_bfloat16 hi = __float2bfloat16(v);
    __nv_bfloat16 lo = __float2bfloat16(v - __bfloat162float(hi));
    int dst = (ls << 14) + j * 128 + k;   // transposed [j][k]
    g_Wthi[dst] = hi;
    g_Wtlo[dst] = lo;
}

__global__ void convx_kernel(const float* __restrict__ x) {
    int i = blockIdx.x * blockDim.x + threadIdx.x;
    if (i >= N_NODES * 32) return;
    float4 v = ((const float4*)x)[i];
    union { __nv_bfloat16 h[4]; uint2 u; } hi, lo;
    float f[4] = { v.x, v.y, v.z, v.w };
#pragma unroll
    for (int q = 0; q < 4; q++) {
        hi.h[q] = __float2bfloat16(f[q]);
        lo.h[q] = __float2bfloat16(f[q] - __bfloat162float(hi.h[q]));
    }
    ((uint2*)g_Xhi)[i] = hi.u;
    ((uint2*)g_Xlo)[i] = lo.u;
}

// --------------------------- HMMA GEMM ------------------------------
// Y[m, s*128 + j] = sum_k X[m,k] * W[s,k,j]  via bf16 hi/lo split:
//   D = Ah@Bh^T + Ah@Bl^T + Al@Bh^T   (Bt[j][k] = W[k][j])
// Block tile 128x128x128; 8 warps as 2(M)x4(N); warp tile 64x32.
__device__ __forceinline__ void prefetch_A(const __nv_bfloat16* __restrict__ Xhi,
                                           const __nv_bfloat16* __restrict__ Xlo,
                                           uint32_t aAhi, uint32_t aAlo,
                                           int m0, int tid) {
#pragma unroll
    for (int p = 0; p < 8; p++) {
        int idx = tid + p * 256;
        int row = idx >> 4, c = idx & 15;
        int gm = m0 + row;
        int ok = gm < N_NODES;
        int gms = ok ? gm : (N_NODES - 1);
        int sz = ok ? 16 : 0;
        uint32_t d = (uint32_t)(row * SROW + c * 16);
        cp_async16(aAhi + d, Xhi + (size_t)gms * EMB + c * 8, sz);
        cp_async16(aAlo + d, Xlo + (size_t)gms * EMB + c * 8, sz);
    }
    CP_COMMIT();
}

__global__ void __launch_bounds__(256) gemmh_kernel(
        const __nv_bfloat16* __restrict__ Xhi,
        const __nv_bfloat16* __restrict__ Xlo,
        int layer) {
    extern __shared__ char dsm[];
    uint32_t sb = smem_u32(dsm);
    int tid = threadIdx.x, wid = tid >> 5, lane = tid & 31;
    int warp_m = wid & 1;          // 0..1 -> 64 rows each
    int warp_n = wid >> 1;         // 0..3 -> 32 cols each

    int per = (TILES_TOT + gridDim.x - 1) / gridDim.x;
    int t0 = blockIdx.x * per;
    int t1 = t0 + per; if (t1 > TILES_TOT) t1 = TILES_TOT;
    if (t0 >= t1) return;

    const __nv_bfloat16* WThi = g_Wthi + (size_t)layer * NW * EMB * EMB;
    const __nv_bfloat16* WTlo = g_Wtlo + (size_t)layer * NW * EMB * EMB;

    int s_cur = -1;
    int buf = 0;
    {
        int s0 = t0 / TILES_M;
        int m0 = (t0 - s0 * TILES_M) * 128;
        prefetch_A(Xhi, Xlo, sb + OFF_AHI, sb + OFF_ALO, m0, tid);
    }

    for (int t = t0; t < t1; t++) {
        int s = t / TILES_M;
        int m0 = (t - s * TILES_M) * 128;

        if (s != s_cur) {
            s_cur = s;
            __syncthreads();   // everyone done reading old B
            const __nv_bfloat16* bh = WThi + s * (EMB * EMB);
            const __nv_bfloat16* bl = WTlo + s * (EMB * EMB);
#pragma unroll
            for (int p = 0; p < 8; p++) {
                int idx = tid + p * 256;
                int row = idx >> 4, c = idx & 15;
                uint32_t d = (uint32_t)(row * SROW + c * 16);
                *(uint4*)(dsm + OFF_BHI + d) = *(const uint4*)(bh + row * 128 + c * 8);
                *(uint4*)(dsm + OFF_BLO + d) = *(const uint4*)(bl + row * 128 + c * 8);
            }
        }

        CP_WAIT0();
        __syncthreads();   // A(t) + B visible

        if (t + 1 < t1) {
            int sn = (t + 1) / TILES_M;
            int mn = ((t + 1) - sn * TILES_M) * 128;
            prefetch_A(Xhi, Xlo, sb + OFF_AHI + (buf ^ 1) * ATILE,
                       sb + OFF_ALO + (buf ^ 1) * ATILE, mn, tid);
        }

        uint32_t abh = sb + OFF_AHI + buf * ATILE;
        uint32_t bbh = sb + OFF_BHI;

        float acc[4][4][4];
#pragma unroll
        for (int mi = 0; mi < 4; mi++)
#pragma unroll
            for (int ni = 0; ni < 4; ni++)
#pragma unroll
                for (int q = 0; q < 4; q++) acc[mi][ni][q] = 0.f;

        // per-thread ldmatrix address components
        uint32_t a_off = (uint32_t)((warp_m * 64 + (lane & 15)) * SROW + ((lane >> 4) * 8) * 2);
        int bm = lane >> 3;
        uint32_t b_row = (uint32_t)(warp_n * 32 + ((bm >> 1) << 3) + (lane & 7));
        uint32_t b_col = (uint32_t)((bm & 1) * 8);

        for (int ks = 0; ks < 8; ks++) {
            uint32_t k2 = (uint32_t)(ks * 16 * 2);
            uint32_t Ah[4][4], Al[4][4];
#pragma unroll
            for (int mi = 0; mi < 4; mi++) {
                uint32_t ad = abh + a_off + (uint32_t)(mi * 16 * SROW) + k2;
                ldsm_x4(Ah[mi], ad);
                ldsm_x4(Al[mi], ad + (OFF_ALO - OFF_AHI));
            }
            uint32_t Bh[4][2], Bl[4][2];
#pragma unroll
            for (int nj = 0; nj < 2; nj++) {
                uint32_t bd = bbh + (b_row + nj * 16) * SROW + b_col * 2 + k2;
                uint32_t r[4];
                ldsm_x4(r, bd);
                Bh[nj * 2][0] = r[0]; Bh[nj * 2][1] = r[1];
                Bh[nj * 2 + 1][0] = r[2]; Bh[nj * 2 + 1][1] = r[3];
                ldsm_x4(r, bd + (OFF_BLO - OFF_BHI));
                Bl[nj * 2][0] = r[0]; Bl[nj * 2][1] = r[1];
                Bl[nj * 2 + 1][0] = r[2]; Bl[nj * 2 + 1][1] = r[3];
            }
#pragma unroll
            for (int mi = 0; mi < 4; mi++)
#pragma unroll
                for (int ni = 0; ni < 4; ni++) {
                    mma_bf16(acc[mi][ni], Ah[mi], Bh[ni]);
                    mma_bf16(acc[mi][ni], Ah[mi], Bl[ni]);
                    mma_bf16(acc[mi][ni], Al[mi], Bh[ni]);
                }
        }

        // epilogue: direct STG to g_Y
        int rbase = m0 + warp_m * 64 + (lane >> 2);
        int cbase = s * EMB + warp_n * 32 + (lane & 3) * 2;
#pragma unroll
        for (int mi = 0; mi < 4; mi++) {
            int r = rbase + mi * 16;
#pragma unroll
            for (int ni = 0; ni < 4; ni++) {
                int c = cbase + ni * 8;
                if (r < N_NODES)
                    *(float2*)(g_Y + (size_t)r * YSTRIDE + c) =
                        make_float2(acc[mi][ni][0], acc[mi][ni][1]);
                if (r + 8 < N_NODES)
                    *(float2*)(g_Y + (size_t)(r + 8) * YSTRIDE + c) =
                        make_float2(acc[mi][ni][2], acc[mi][ni][3]);
            }
        }
        buf ^= 1;
        __syncthreads();   // done with this A buf before it's refilled 2 iters later
    }
}

// --------------------------- node epilogue -----------------------------
__global__ void __launch_bounds__(256) node_kernel(const float* __restrict__ bl,
                                                   float* __restrict__ Xout,
                                                   int do_relu) {
    int warp = (blockIdx.x << 3) + (threadIdx.x >> 5);
    if (warp >= N_NODES) return;
    int i  = warp;
    int fo = (threadIdx.x & 31) << 2;

    float Ai = g_A[i];
    float4 acc;
    {
        float4 ys  = *(const float4*)(g_Y + (size_t)i * YSTRIDE + S_REL * EMB + fo);
        float4 b18 = *(const float4*)(bl + S_REL * EMB + fo);
        acc.x = Ai * (ys.x + b18.x);
        acc.y = Ai * (ys.y + b18.y);
        acc.z = Ai * (ys.z + b18.z);
        acc.w = Ai * (ys.w + b18.w);
    }
#pragma unroll
    for (int s = 0; s < S_REL; s++) {
        float g = g_gamma[s * N_NODES + i];
        float4 bs = *(const float4*)(bl + s * EMB + fo);
        acc.x = fmaf(g, bs.x, acc.x);
        acc.y = fmaf(g, bs.y, acc.y);
        acc.z = fmaf(g, bs.z, acc.z);
        acc.w = fmaf(g, bs.w, acc.w);
    }
    int e0 = g_off[i], e1 = g_off[i + 1];
    for (int e = e0; e < e1; e++) {
        int rec = g_rec[e];
        int src = rec & 0xFFFF;
        int s   = rec >> 16;
        float al = g_alpha[s * N_NODES + i];
        float4 y = *(const float4*)(g_Y + (size_t)src * YSTRIDE + (s << 7) + fo);
        acc.x = fmaf(al, y.x, acc.x);
        acc.y = fmaf(al, y.y, acc.y);
        acc.z = fmaf(al, y.z, acc.z);
        acc.w = fmaf(al, y.w, acc.w);
    }
    if (do_relu) {
        acc.x = fmaxf(acc.x, 0.f);
        acc.y = fmaxf(acc.y, 0.f);
        acc.z = fmaxf(acc.z, 0.f);
        acc.w = fmaxf(acc.w, 0.f);
    }
    *(float4*)(Xout + (size_t)i * EMB + fo) = acc;
}

// ------------------------------ launch ---------------------------------
extern "C" void kernel_launch(void* const* d_in, const int* in_sizes, int n_in,
                              void* d_out, int out_size) {
    const int*   ei  = (const int*)d_in[0];     // [2, E]
    const int*   et  = (const int*)d_in[1];     // [E]
    const float* emb = (const float*)d_in[2];   // [N, 128]
    const float* w   = (const float*)d_in[3];   // [2, 19, 128, 128]
    const float* b   = (const float*)d_in[4];   // [2, 19, 128]
    float* out = (float*)d_out;

    float* hptr = nullptr;
    cudaGetSymbolAddress((void**)&hptr, g_H);
    __nv_bfloat16* xhi = nullptr;
    __nv_bfloat16* xlo = nullptr;
    cudaGetSymbolAddress((void**)&xhi, g_Xhi);
    cudaGetSymbolAddress((void**)&xlo, g_Xlo);

    cudaFuncSetAttribute(gemmh_kernel,
                         cudaFuncAttributeMaxDynamicSharedMemorySize, GEMM_DSM);

    zero_kernel<<<512, 256>>>();
    hist_kernel<<<(E2 + 255) / 256, 256>>>(ei, et);
    alpha_kernel<<<(N_NODES + 255) / 256, 256>>>();
    int nb = (N_NODES + 1023) / 1024;
    scan1_kernel<<<nb, 1024>>>();
    scan2_kernel<<<1, 32>>>(nb);
    scan3_kernel<<<(N_NODES + 255) / 256, 256>>>();
    scatter_kernel<<<(E2 + 255) / 256, 256>>>(ei, et);

    convw_kernel<<<(2 * NW * EMB * EMB + 255) / 256, 256>>>(w);

    int ngrid = (N_NODES + 7) / 8;
    int cgrid = (N_NODES * 32 + 255) / 256;

    // layer 0
    convx_kernel<<<cgrid, 256>>>(emb);
    gemmh_kernel<<<148, 256, GEMM_DSM>>>(xhi, xlo, 0);
    node_kernel<<<ngrid, 256>>>(b, hptr, 1);
    // layer 1
    convx_kernel<<<cgrid, 256>>>(hptr);
    gemmh_kernel<<<148, 256, GEMM_DSM>>>(xhi, xlo, 1);
    node_kernel<<<ngrid, 256>>>(b + B_LAYER, out, 0);
}